// round 3
// baseline (speedup 1.0000x reference)
#include <cuda_runtime.h>

// Problem constants
#define BB     256      // batch
#define SEQ    196
#define DD     768
#define NPOOL  20       // per pool (s and m identical)
#define NKEYS  40       // 20 s-keys + 20 m-keys
#define KK     4        // top-k
#define BLK    3840     // LEN*H*DH = 5*12*64 floats per selected pool entry
#define PER_LB 15360    // KK * BLK floats per (layer, batch)
#define L2N    24       // num_layers * 2

// Tiny device-global scratch (no allocations allowed)
__device__ float g_keys[NKEYS * DD];     // normalized keys (s then m)
__device__ float g_sim[BB * NKEYS];      // similarities
__device__ int   g_sidx[BB * KK];
__device__ int   g_midx[BB * KK];

// ---------------------------------------------------------------------------
// Kernel 1: L2-normalize the 40 prompt keys. 40 blocks x 256 threads.
// ---------------------------------------------------------------------------
__global__ void normalize_keys_kernel(const float* __restrict__ skey,
                                      const float* __restrict__ mkey) {
    int p = blockIdx.x;  // 0..39
    const float* src = (p < NPOOL) ? (skey + (size_t)p * DD)
                                   : (mkey + (size_t)(p - NPOOL) * DD);
    int t = threadIdx.x;  // 256 threads, 3 columns each
    float v0 = src[t], v1 = src[t + 256], v2 = src[t + 512];
    float sq = v0 * v0 + v1 * v1 + v2 * v2;

    __shared__ float sh[8];
    #pragma unroll
    for (int o = 16; o > 0; o >>= 1) sq += __shfl_down_sync(0xffffffffu, sq, o);
    if ((t & 31) == 0) sh[t >> 5] = sq;
    __syncthreads();
    if (t < 8) {
        float s = sh[t];
        #pragma unroll
        for (int o = 4; o > 0; o >>= 1) s += __shfl_down_sync(0xffu, s, o);
        if (t == 0) sh[0] = s;
    }
    __syncthreads();
    float inv = rsqrtf(fmaxf(sh[0], 1e-12f));
    float* dst = g_keys + (size_t)p * DD;
    dst[t] = v0 * inv;
    dst[t + 256] = v1 * inv;
    dst[t + 512] = v2 * inv;
}

// ---------------------------------------------------------------------------
// Kernel 2: per-batch mean over SEQ, L2-normalize, and 40 dot products.
// 256 blocks x 768 threads (one thread per feature column).
// ---------------------------------------------------------------------------
__global__ void batch_sim_kernel(const float* __restrict__ x) {
    int b = blockIdx.x;
    int d = threadIdx.x;            // 0..767
    const float* xb = x + (size_t)b * (SEQ * DD) + d;

    float acc = 0.f;
    #pragma unroll 4
    for (int s = 0; s < SEQ; ++s) acc += xb[(size_t)s * DD];
    float mean = acc * (1.0f / SEQ);

    __shared__ float shw[32];
    __shared__ float sh_x[DD];

    float sq = mean * mean;
    #pragma unroll
    for (int o = 16; o > 0; o >>= 1) sq += __shfl_down_sync(0xffffffffu, sq, o);
    int warp = d >> 5, lane = d & 31;
    if (lane == 0) shw[warp] = sq;
    __syncthreads();
    if (d < 32) {
        float s = (d < 24) ? shw[d] : 0.f;
        #pragma unroll
        for (int o = 16; o > 0; o >>= 1) s += __shfl_down_sync(0xffffffffu, s, o);
        if (d == 0) shw[0] = s;
    }
    __syncthreads();
    float inv = rsqrtf(fmaxf(shw[0], 1e-12f));
    sh_x[d] = mean * inv;
    __syncthreads();

    // 24 warps handle 40 pools
    for (int p = warp; p < NKEYS; p += 24) {
        const float* kp = g_keys + (size_t)p * DD;
        float dot = 0.f;
        #pragma unroll
        for (int i = lane; i < DD; i += 32) dot += sh_x[i] * kp[i];
        #pragma unroll
        for (int o = 16; o > 0; o >>= 1) dot += __shfl_down_sync(0xffffffffu, dot, o);
        if (lane == 0) g_sim[b * NKEYS + p] = dot;
    }
}

// ---------------------------------------------------------------------------
// Kernel 3: top-4 selection per batch (jax top_k order: descending, first-
// index ties) + deterministic block reduction of the two reduce_sim scalars.
// 1 block x 256 threads (one thread per batch row).
// ---------------------------------------------------------------------------
__global__ void topk_kernel(float* __restrict__ out_scalars) {
    int b = threadIdx.x;  // 0..255
    float vs[NPOOL], vm[NPOOL];
    #pragma unroll
    for (int j = 0; j < NPOOL; ++j) {
        vs[j] = g_sim[b * NKEYS + j];
        vm[j] = g_sim[b * NKEYS + NPOOL + j];
    }
    float ssum = 0.f, msum = 0.f;
    #pragma unroll
    for (int k = 0; k < KK; ++k) {
        float best = -1e30f; int bi = 0;
        #pragma unroll
        for (int j = 0; j < NPOOL; ++j) if (vs[j] > best) { best = vs[j]; bi = j; }
        g_sidx[b * KK + k] = bi; ssum += best; vs[bi] = -1e30f;

        best = -1e30f; bi = 0;
        #pragma unroll
        for (int j = 0; j < NPOOL; ++j) if (vm[j] > best) { best = vm[j]; bi = j; }
        g_midx[b * KK + k] = bi; msum += best; vm[bi] = -1e30f;
    }

    __shared__ float shs[8], shm[8];
    #pragma unroll
    for (int o = 16; o > 0; o >>= 1) {
        ssum += __shfl_down_sync(0xffffffffu, ssum, o);
        msum += __shfl_down_sync(0xffffffffu, msum, o);
    }
    if ((b & 31) == 0) { shs[b >> 5] = ssum; shm[b >> 5] = msum; }
    __syncthreads();
    if (b < 8) {
        float s = shs[b], m = shm[b];
        #pragma unroll
        for (int o = 4; o > 0; o >>= 1) {
            s += __shfl_down_sync(0xffu, s, o);
            m += __shfl_down_sync(0xffu, m, o);
        }
        if (b == 0) {
            out_scalars[0] = s * (1.0f / BB);
            out_scalars[1] = m * (1.0f / BB);
        }
    }
}

// ---------------------------------------------------------------------------
// Kernel 4: the gather. The reshape in the reference is a pure row-major
// reinterpretation, so output[(l,b)] is the concatenation of 4 contiguous
// 3840-float blocks prompt[l, idx[b,k]]. float4 copies, fully coalesced.
// Grid: L2N*BB = 6144 blocks x 256 threads. which: 0 = s, 1 = m.
// ---------------------------------------------------------------------------
__global__ void gather_kernel(const float4* __restrict__ prompt,
                              float4* __restrict__ out, int which) {
    int lb = blockIdx.x;
    int l = lb >> 8;          // / 256
    int b = lb & 255;
    int t = threadIdx.x;
    const int* idx = which ? g_midx : g_sidx;
    int i0 = idx[b * KK + 0], i1 = idx[b * KK + 1],
        i2 = idx[b * KK + 2], i3 = idx[b * KK + 3];
    int ids[4] = {i0, i1, i2, i3};

    float4* dst = out + (size_t)lb * (PER_LB / 4);
    #pragma unroll
    for (int k = 0; k < 4; ++k) {
        const float4* src = prompt + ((size_t)l * NPOOL + ids[k]) * (BLK / 4);
        float4* dk = dst + k * (BLK / 4);
        for (int j = t; j < BLK / 4; j += 256)   // 960 float4 per chunk
            dk[j] = src[j];
    }
}

// ---------------------------------------------------------------------------
extern "C" void kernel_launch(void* const* d_in, const int* in_sizes, int n_in,
                              void* d_out, int out_size) {
    const float* x_embed = (const float*)d_in[0];  // [256,196,768]
    const float* s_prompt = (const float*)d_in[1]; // [24,20,5,12,64]
    const float* m_prompt = (const float*)d_in[2]; // [24,20,5,12,64]
    const float* s_key = (const float*)d_in[3];    // [20,768]
    const float* m_key = (const float*)d_in[4];    // [20,768]
    float* out = (float*)d_out;

    const size_t S_ELEMS = (size_t)L2N * BB * PER_LB;  // 94,371,840

    normalize_keys_kernel<<<NKEYS, 256>>>(s_key, m_key);
    batch_sim_kernel<<<BB, DD>>>(x_embed);
    topk_kernel<<<1, 256>>>(out + 2 * S_ELEMS);
    gather_kernel<<<L2N * BB, 256>>>((const float4*)s_prompt,
                                     (float4*)out, 0);
    gather_kernel<<<L2N * BB, 256>>>((const float4*)m_prompt,
                                     (float4*)(out + S_ELEMS), 1);
}